// round 13
// baseline (speedup 1.0000x reference)
#include <cuda_runtime.h>
#include <cuda_fp16.h>
#include <math.h>

// Problem constants
#define Tn 128
#define Bn 1024
#define In 128
#define Hn 256
#define Kn 8
#define E1n 512
#define E2n 256
#define NCTA 128
#define NGRP 16

// smem strides for mma GRU (bank-conflict-free fragment loads)
#define WST 108
#define HST 260

// ---------------- device scratch (no allocations allowed) ----------------
__device__ __align__(256) __half g_gi16[(size_t)Tn * Bn * 3 * Hn];   // 201 MB
__device__ __align__(256) __half g_hseq16[(size_t)Tn * Bn * Hn];     // 67 MB
__device__ __align__(256) float g_hbuf0[Bn * Hn];
__device__ __align__(256) float g_hbuf1[Bn * Hn];
__device__ __align__(256) float g_q[Bn * Kn];
__device__ __align__(256) float g_Wt_ih0[In * 3 * Hn];
__device__ __align__(256) float g_Wt_ih1[Hn * 3 * Hn];
__device__ __align__(256) float g_wp0[8 * Hn * 96];
__device__ __align__(256) float g_wp1[8 * Hn * 96];
__device__ __align__(256) float g_bsum0[3 * Hn];
__device__ __align__(256) float g_bsum1[3 * Hn];
__device__ __align__(256) float g_Wt_e1[Kn * Hn * E1n];
__device__ __align__(256) float g_Wt_e2[Kn * E1n * E2n];
__device__ __align__(256) float g_h1[(size_t)Kn * Bn * E1n];
__device__ __align__(256) float g_h2[(size_t)Kn * Bn * E2n];

// per-(group, producer) monotonic arrive counters + per-group done counters
__device__ __align__(256) unsigned g_arr[NGRP * 8 * 32];   // 128B stride per counter
__device__ __align__(256) unsigned g_done[NGRP * 32];

// ---------------- f32x2 packed math helpers (Blackwell FFMA2) ----------------
__device__ __forceinline__ unsigned long long pack2(float x, float y) {
    unsigned long long r;
    asm("mov.b64 %0, {%1, %2};" : "=l"(r) : "f"(x), "f"(y));
    return r;
}
__device__ __forceinline__ void ffma2(unsigned long long& d, unsigned long long a, unsigned long long b) {
    asm("fma.rn.f32x2 %0, %1, %2, %0;" : "+l"(d) : "l"(a), "l"(b));
}
__device__ __forceinline__ float2 unpack2(unsigned long long v) {
    float2 f;
    asm("mov.b64 {%0, %1}, %2;" : "=f"(f.x), "=f"(f.y) : "l"(v));
    return f;
}
__device__ __forceinline__ void wait_ge(const unsigned* p, unsigned v) {
    unsigned x;
    asm volatile("ld.acquire.gpu.global.u32 %0, [%1];" : "=r"(x) : "l"(p) : "memory");
    while (x < v) {
        __nanosleep(64);
        asm volatile("ld.acquire.gpu.global.u32 %0, [%1];" : "=r"(x) : "l"(p) : "memory");
    }
}
__device__ __forceinline__ void red_release_add1(unsigned* p) {
    asm volatile("red.release.gpu.global.add.u32 [%0], %1;" :: "l"(p), "r"(1u) : "memory");
}

// ---------------- tf32 mma helpers ----------------
__device__ __forceinline__ unsigned f2tf32(float x) {
    unsigned u;
    asm("cvt.rna.tf32.f32 %0, %1;" : "=r"(u) : "f"(x));
    return u;
}
__device__ __forceinline__ void mma_tf32(float* c, const unsigned* a, const unsigned* b) {
    asm volatile(
        "mma.sync.aligned.m16n8k8.row.col.f32.tf32.tf32.f32 "
        "{%0,%1,%2,%3}, {%4,%5,%6,%7}, {%8,%9}, {%0,%1,%2,%3};"
        : "+f"(c[0]), "+f"(c[1]), "+f"(c[2]), "+f"(c[3])
        : "r"(a[0]), "r"(a[1]), "r"(a[2]), "r"(a[3]), "r"(b[0]), "r"(b[1]));
}

// load 4 consecutive A elements (fp32 or fp16) -> tf32 bits
__device__ __forceinline__ uint4 loadA4_tf32(const void* A, int ahalf, size_t idx) {
    if (ahalf) {
        const __half* Ah = (const __half*)A + idx;
        float2 f01 = __half22float2(*(const __half2*)Ah);
        float2 f23 = __half22float2(*(const __half2*)(Ah + 2));
        return make_uint4(f2tf32(f01.x), f2tf32(f01.y), f2tf32(f23.x), f2tf32(f23.y));
    } else {
        float4 v = *(const float4*)((const float*)A + idx);
        return make_uint4(f2tf32(v.x), f2tf32(v.y), f2tf32(v.z), f2tf32(v.w));
    }
}

// ---------------- fused transpose (all weight transposes in ONE launch) ----------------
struct TJob { const float* in; float* out; int R, C, tC, tpb, off; };
struct TJobs { TJob j[4]; };

__global__ void transpose_all(TJobs js)
{
    __shared__ float tile[32][33];
    int bx = blockIdx.x;
    int ji = 0;
    if (bx >= js.j[1].off) ji = 1;
    if (bx >= js.j[2].off) ji = 2;
    if (bx >= js.j[3].off) ji = 3;
    TJob jb = js.j[ji];
    int local = bx - jb.off;
    int batch = local / jb.tpb;
    int rem = local - batch * jb.tpb;
    int cIdx = rem % jb.tC, rIdx = rem / jb.tC;
    size_t boff = (size_t)batch * jb.R * jb.C;
    int c0 = cIdx * 32, r0 = rIdx * 32;
    int tx = threadIdx.x, ty = threadIdx.y;
    #pragma unroll
    for (int i = ty; i < 32; i += 8)
        tile[i][tx] = jb.in[boff + (size_t)(r0 + i) * jb.C + c0 + tx];
    __syncthreads();
    #pragma unroll
    for (int i = ty; i < 32; i += 8)
        jb.out[boff + (size_t)(c0 + i) * jb.R + r0 + tx] = tile[tx][i];
}

// ---------------- pack W_hh into per-nblk contiguous [nblk][k][96] ----------------
__global__ void pack_whh(const float* __restrict__ W0, const float* __restrict__ W1,
                         float* __restrict__ P0, float* __restrict__ P1)
{
    const float* W = blockIdx.z ? W1 : W0;
    float* P = blockIdx.z ? P1 : P0;
    int nblk = blockIdx.x, k0 = blockIdx.y * 32;
    __shared__ float tile[96][33];
    int tx = threadIdx.x & 31, ty = threadIdx.x >> 5;  // 32 x 8
    for (int j = ty; j < 96; j += 8) {
        int row = (j >> 5) * Hn + nblk * 32 + (j & 31);
        tile[j][tx] = W[(size_t)row * Hn + k0 + tx];
    }
    __syncthreads();
    for (int idx = threadIdx.x; idx < 32 * 96; idx += 256) {
        int kk = idx / 96, c = idx - kk * 96;
        P[((size_t)nblk * Hn + k0 + kk) * 96 + c] = tile[c][kk];
    }
}

// ---------------- bias combine (one layer per launch) ----------------
__global__ void bias_one(const float* bih, const float* bhh, float* o)
{
    int i = threadIdx.x;  // 768
    o[i] = bih[i] + (i < 2 * Hn ? bhh[i] : 0.f);
}

// ---------------- tf32 tensor-core GEMM: C = A @ Bt + bias ----------------
// A fp32 or fp16 (ahalf); C fp32 or fp16 (outhalf); tf32 conversion at fill time.
__global__ __launch_bounds__(256, 2) void gemm_tf32(
    const void* __restrict__ Avoid, const float* __restrict__ Bt,
    const float* __restrict__ bias, void* __restrict__ Cvoid,
    int M, int N, int K, int lda, int amode, int ahalf, int outhalf)
{
    __shared__ unsigned As[2][128][20];
    __shared__ unsigned Bs[2][16][136];

    const int n0 = blockIdx.x * 128;
    const int m0 = blockIdx.y * 128;
    const int tid = threadIdx.x;
    const int lane = tid & 31, w = tid >> 5;
    const int wm0 = (w >> 2) * 64, wn0 = (w & 3) * 32;
    const int gid = lane >> 2, tig = lane & 3;

    const int arow0 = tid >> 2, aq = tid & 3;
    const int brow0 = tid >> 5, bq = tid & 31;

    size_t ab0, ab1;
    { int m = m0 + arow0;
      ab0 = (amode == 0) ? (size_t)m * lda
                         : ((size_t)(m & (Bn - 1)) * Tn + (m >> 10)) * (size_t)lda; }
    { int m = m0 + arow0 + 64;
      ab1 = (amode == 0) ? (size_t)m * lda
                         : ((size_t)(m & (Bn - 1)) * Tn + (m >> 10)) * (size_t)lda; }
    const size_t ai0 = ab0 + aq * 4;
    const size_t ai1 = ab1 + aq * 4;
    const float* Bp0 = Bt + (size_t)brow0 * N + n0 + bq * 4;
    const float* Bp1 = Bt + (size_t)(brow0 + 8) * N + n0 + bq * 4;

    float c[4][4][4];
    #pragma unroll
    for (int mi = 0; mi < 4; mi++)
        #pragma unroll
        for (int ni = 0; ni < 4; ni++)
            #pragma unroll
            for (int r = 0; r < 4; r++) c[mi][ni][r] = 0.f;

    uint4 pa0 = loadA4_tf32(Avoid, ahalf, ai0);
    uint4 pa1 = loadA4_tf32(Avoid, ahalf, ai1);
    float4 pb0 = *(const float4*)(Bp0);
    float4 pb1 = *(const float4*)(Bp1);
    *(uint4*)&As[0][arow0][aq * 4] = pa0;
    *(uint4*)&As[0][arow0 + 64][aq * 4] = pa1;
    *(uint4*)&Bs[0][brow0][bq * 4] = make_uint4(f2tf32(pb0.x), f2tf32(pb0.y), f2tf32(pb0.z), f2tf32(pb0.w));
    *(uint4*)&Bs[0][brow0 + 8][bq * 4] = make_uint4(f2tf32(pb1.x), f2tf32(pb1.y), f2tf32(pb1.z), f2tf32(pb1.w));
    __syncthreads();

    const int nit = K >> 4;
    for (int it = 0; it < nit; ++it) {
        const int cur = it & 1;
        const bool more = (it + 1) < nit;
        if (more) {
            const int k0 = (it + 1) << 4;
            pa0 = loadA4_tf32(Avoid, ahalf, ai0 + k0);
            pa1 = loadA4_tf32(Avoid, ahalf, ai1 + k0);
            pb0 = *(const float4*)(Bp0 + (size_t)k0 * N);
            pb1 = *(const float4*)(Bp1 + (size_t)k0 * N);
        }
        #pragma unroll
        for (int ks = 0; ks < 2; ks++) {
            const int ac = ks * 8 + tig;
            unsigned af[4][4];
            #pragma unroll
            for (int mi = 0; mi < 4; mi++) {
                const int rb = wm0 + mi * 16 + gid;
                af[mi][0] = As[cur][rb][ac];
                af[mi][1] = As[cur][rb + 8][ac];
                af[mi][2] = As[cur][rb][ac + 4];
                af[mi][3] = As[cur][rb + 8][ac + 4];
            }
            const int bk = ks * 8 + tig;
            unsigned bf[4][2];
            #pragma unroll
            for (int ni = 0; ni < 4; ni++) {
                const int nn = wn0 + ni * 8 + gid;
                bf[ni][0] = Bs[cur][bk][nn];
                bf[ni][1] = Bs[cur][bk + 4][nn];
            }
            #pragma unroll
            for (int mi = 0; mi < 4; mi++)
                #pragma unroll
                for (int ni = 0; ni < 4; ni++)
                    mma_tf32(c[mi][ni], af[mi], bf[ni]);
        }
        if (more) {
            const int nb = cur ^ 1;
            *(uint4*)&As[nb][arow0][aq * 4] = pa0;
            *(uint4*)&As[nb][arow0 + 64][aq * 4] = pa1;
            *(uint4*)&Bs[nb][brow0][bq * 4] = make_uint4(f2tf32(pb0.x), f2tf32(pb0.y), f2tf32(pb0.z), f2tf32(pb0.w));
            *(uint4*)&Bs[nb][brow0 + 8][bq * 4] = make_uint4(f2tf32(pb1.x), f2tf32(pb1.y), f2tf32(pb1.z), f2tf32(pb1.w));
            __syncthreads();
        }
    }

    #pragma unroll
    for (int ni = 0; ni < 4; ni++) {
        const int cc = n0 + wn0 + ni * 8 + tig * 2;
        const float2 b2 = *(const float2*)&bias[cc];
        #pragma unroll
        for (int mi = 0; mi < 4; mi++) {
            const int r = m0 + wm0 + mi * 16 + gid;
            float2 v0 = make_float2(c[mi][ni][0] + b2.x, c[mi][ni][1] + b2.y);
            float2 v1 = make_float2(c[mi][ni][2] + b2.x, c[mi][ni][3] + b2.y);
            if (outhalf) {
                *(__half2*)((__half*)Cvoid + (size_t)r * N + cc) = __float22half2_rn(v0);
                *(__half2*)((__half*)Cvoid + (size_t)(r + 8) * N + cc) = __float22half2_rn(v1);
            } else {
                *(float2*)((float*)Cvoid + (size_t)r * N + cc) = v0;
                *(float2*)((float*)Cvoid + (size_t)(r + 8) * N + cc) = v1;
            }
        }
    }
}

// ---------------- double-buffered 128x128x16 fp32x2 GEMM (experts, exact) ----------------
__global__ __launch_bounds__(256, 2) void gemm128(
    const float* __restrict__ A, const float* __restrict__ Bt,
    const float* __restrict__ bias, float* __restrict__ Cmat,
    int M, int N, int K, int lda, int amode, int relu,
    long long sA, long long sB, long long sBias, long long sC)
{
    const int bz = blockIdx.z;
    A    += (size_t)sA * bz;
    Bt   += (size_t)sB * bz;
    bias += (size_t)sBias * bz;
    Cmat += (size_t)sC * bz;
    const int n0 = blockIdx.x * 128;
    const int m0 = blockIdx.y * 128;

    __shared__ float As[2][16][132];
    __shared__ float Bs[2][16][128];

    const int tid = threadIdx.x;
    const int tx = tid & 15, ty = tid >> 4;
    const int arow0 = tid >> 2, aq = tid & 3;
    const int brow0 = tid >> 5, bq = tid & 31;

    size_t ab0 = (size_t)(m0 + arow0) * lda;
    size_t ab1 = (size_t)(m0 + arow0 + 64) * lda;
    const float* Ap0 = A + ab0 + aq * 4;
    const float* Ap1 = A + ab1 + aq * 4;
    const float* Bp0 = Bt + (size_t)brow0 * N + n0 + bq * 4;
    const float* Bp1 = Bt + (size_t)(brow0 + 8) * N + n0 + bq * 4;

    unsigned long long acc[8][4];
    #pragma unroll
    for (int i = 0; i < 8; i++)
        #pragma unroll
        for (int j = 0; j < 4; j++) acc[i][j] = 0ull;

    float4 pa0 = *(const float4*)(Ap0);
    float4 pa1 = *(const float4*)(Ap1);
    float4 pb0 = *(const float4*)(Bp0);
    float4 pb1 = *(const float4*)(Bp1);
    As[0][aq * 4 + 0][arow0] = pa0.x; As[0][aq * 4 + 1][arow0] = pa0.y;
    As[0][aq * 4 + 2][arow0] = pa0.z; As[0][aq * 4 + 3][arow0] = pa0.w;
    As[0][aq * 4 + 0][arow0 + 64] = pa1.x; As[0][aq * 4 + 1][arow0 + 64] = pa1.y;
    As[0][aq * 4 + 2][arow0 + 64] = pa1.z; As[0][aq * 4 + 3][arow0 + 64] = pa1.w;
    *(float4*)&Bs[0][brow0][bq * 4] = pb0;
    *(float4*)&Bs[0][brow0 + 8][bq * 4] = pb1;
    __syncthreads();

    const int nit = K >> 4;
    for (int it = 0; it < nit; ++it) {
        const int cur = it & 1;
        const bool more = (it + 1) < nit;
        if (more) {
            const int k0 = (it + 1) << 4;
            pa0 = *(const float4*)(Ap0 + k0);
            pa1 = *(const float4*)(Ap1 + k0);
            pb0 = *(const float4*)(Bp0 + (size_t)k0 * N);
            pb1 = *(const float4*)(Bp1 + (size_t)k0 * N);
        }
        #pragma unroll
        for (int k = 0; k < 16; k++) {
            float4 aA = *(const float4*)&As[cur][k][ty * 4];
            float4 aB = *(const float4*)&As[cur][k][64 + ty * 4];
            ulonglong2 bA = *(const ulonglong2*)&Bs[cur][k][tx * 4];
            ulonglong2 bB = *(const ulonglong2*)&Bs[cur][k][64 + tx * 4];
            unsigned long long b2[4] = { bA.x, bA.y, bB.x, bB.y };
            float a_[8] = { aA.x, aA.y, aA.z, aA.w, aB.x, aB.y, aB.z, aB.w };
            #pragma unroll
            for (int i = 0; i < 8; i++) {
                unsigned long long a2 = pack2(a_[i], a_[i]);
                #pragma unroll
                for (int j = 0; j < 4; j++) ffma2(acc[i][j], a2, b2[j]);
            }
        }
        if (more) {
            const int nb = cur ^ 1;
            As[nb][aq * 4 + 0][arow0] = pa0.x; As[nb][aq * 4 + 1][arow0] = pa0.y;
            As[nb][aq * 4 + 2][arow0] = pa0.z; As[nb][aq * 4 + 3][arow0] = pa0.w;
            As[nb][aq * 4 + 0][arow0 + 64] = pa1.x; As[nb][aq * 4 + 1][arow0 + 64] = pa1.y;
            As[nb][aq * 4 + 2][arow0 + 64] = pa1.z; As[nb][aq * 4 + 3][arow0 + 64] = pa1.w;
            *(float4*)&Bs[nb][brow0][bq * 4] = pb0;
            *(float4*)&Bs[nb][brow0 + 8][bq * 4] = pb1;
            __syncthreads();
        }
    }

    #pragma unroll
    for (int i = 0; i < 8; i++) {
        int r = (i < 4) ? (ty * 4 + i) : (64 + ty * 4 + (i - 4));
        size_t crow = (size_t)(m0 + r) * N;
        #pragma unroll
        for (int j = 0; j < 4; j++) {
            int c = n0 + ((j < 2) ? (tx * 4 + j * 2) : (64 + tx * 4 + (j - 2) * 2));
            float2 v = unpack2(acc[i][j]);
            v.x += bias[c]; v.y += bias[c + 1];
            if (relu) { v.x = fmaxf(v.x, 0.f); v.y = fmaxf(v.y, 0.f); }
            *(float2*)&Cmat[crow + c] = v;
        }
    }
}

// ---------------- chunk mma: 4 k-tiles (32 k) of m16n8k8 across 3 gates ----------------
__device__ __forceinline__ void mma_chunk(
    const unsigned* __restrict__ Hs, const unsigned* __restrict__ Ws,
    int j, int mwarp, int slice, int gid, int tig, float (&acc)[2][3][4])
{
    #pragma unroll
    for (int kt = 0; kt < 4; kt++) {
        const int kk = j * 32 + kt * 8;
        unsigned a[2][4];
        #pragma unroll
        for (int mt = 0; mt < 2; mt++) {
            const unsigned* hb = Hs + (mwarp + mt * 16 + gid) * HST + kk + tig;
            a[mt][0] = hb[0];
            a[mt][1] = hb[8 * HST];
            a[mt][2] = hb[4];
            a[mt][3] = hb[8 * HST + 4];
        }
        unsigned bf[3][2];
        #pragma unroll
        for (int g = 0; g < 3; g++) {
            const int n = g * 32 + slice * 8 + gid;
            bf[g][0] = Ws[(kk + tig) * WST + n];
            bf[g][1] = Ws[(kk + tig + 4) * WST + n];
        }
        #pragma unroll
        for (int mt = 0; mt < 2; mt++)
            #pragma unroll
            for (int g = 0; g < 3; g++)
                mma_tf32(acc[mt][g], a[mt], bf[g]);
    }
}

// ---------------- persistent GRU layer: dataflow exchange via fp32 ping-pong ----
// 128 CTAs. bid = grp*8 + nblk. CTA: 64 batch rows x (3 gates x 32 cols), K=256.
// gi is fp16. Exchange always via pb0/pb1 (L2-resident). mode 0 additionally
// stores h(t) to hseq16 (fp16) for the gi1 GEMM.
__global__ __launch_bounds__(256, 1) void gru_layer(
    const __half* __restrict__ gi,   // [T,B,3H] fp16, b_ih + b_hh(r,z) folded
    const float* __restrict__ wpack, // [8][256][96] fp32
    const float* __restrict__ bhh,   // original b_hh (n-gate slice used)
    __half* __restrict__ hseq16,     // [T,B,H] fp16 or nullptr
    float* __restrict__ pb0, float* __restrict__ pb1,
    int mode)
{
    extern __shared__ unsigned smu[];
    unsigned* Ws = smu;                 // [256][WST] tf32 bits
    unsigned* Hs = smu + 256 * WST;     // [64][HST]  tf32 bits

    const int bid = blockIdx.x;
    const int nblk = bid & 7;
    const int grp = bid >> 3;
    const int b0 = grp << 6;
    const int tid = threadIdx.x;
    const int lane = tid & 31, w = tid >> 5;
    const int gid = lane >> 2, tig = lane & 3;
    const int slice = w & 3;
    const int mwarp = (w >> 2) * 32;
    const int grp8 = grp * 8;

    // chunk-fill thread mapping (2 float4 per thread per chunk)
    const int fr0 = tid >> 3, fq0 = tid & 7;
    const int fr1 = 32 + (tid >> 3), fq1 = tid & 7;

    // load W slice once, convert to tf32, restride 96 -> WST
    {
        const float* wsrc = wpack + (size_t)nblk * 256 * 96;
        for (int i = tid; i < 256 * 24; i += 256) {
            int k = i / 24, c4 = (i - (i / 24) * 24) * 4;
            float4 v = *(const float4*)(wsrc + (size_t)k * 96 + c4);
            *(uint4*)&Ws[k * WST + c4] = make_uint4(f2tf32(v.x), f2tf32(v.y), f2tf32(v.z), f2tf32(v.w));
        }
    }
    __syncthreads();

    const int n0c = (nblk << 5) + slice * 8 + tig * 2;   // owned global hidden cols
    const float2 bn2 = *(const float2*)&bhh[2 * Hn + n0c];

    float hpr[4][2];   // own h(t-1) values (this thread's previous outputs)
    #pragma unroll
    for (int i = 0; i < 4; i++) { hpr[i][0] = 0.f; hpr[i][1] = 0.f; }

    for (int t = 0; t < Tn; t++) {
        const float* hprevG = (t & 1) ? pb1 : pb0;
        float* hout = (t & 1) ? pb0 : pb1;

        // hoisted gi loads (fp16, independent of peers)
        float2 gr[4], gz[4], gn[4];
        #pragma unroll
        for (int idx = 0; idx < 4; idx++) {
            int b = b0 + mwarp + (idx >> 1) * 16 + (idx & 1) * 8 + gid;
            const __half* gp = gi + ((size_t)t * Bn + b) * (3 * Hn);
            gr[idx] = __half22float2(*(const __half2*)(gp + n0c));
            gz[idx] = __half22float2(*(const __half2*)(gp + Hn + n0c));
            gn[idx] = __half22float2(*(const __half2*)(gp + 2 * Hn + n0c));
        }

        float acc[2][3][4];
        #pragma unroll
        for (int mt = 0; mt < 2; mt++)
            #pragma unroll
            for (int g = 0; g < 3; g++)
                #pragma unroll
                for (int r = 0; r < 4; r++) acc[mt][g][r] = 0.f;

        if (t > 0) {
            // own chunk already in Hs from t-1 epilogue: compute while peers finish
            mma_chunk(Hs, Ws, nblk, mwarp, slice, gid, tig, acc);

            // parallel wait: lanes 0..6 each poll one peer counter
            if (tid < 7) {
                const int pj = (nblk + 1 + tid) & 7;
                wait_ge(&g_arr[(grp8 + pj) * 32], (unsigned)t);
            }
            __syncthreads();

            // batched load of all 7 peer chunks (two register waves), then STS
            uint4 ra[4], rb[4];
            #pragma unroll
            for (int j = 0; j < 4; j++) {
                const int pj = (nblk + 1 + j) & 7;
                float4 v0 = __ldcg((const float4*)(hprevG + (size_t)(b0 + fr0) * Hn + pj * 32 + fq0 * 4));
                float4 v1 = __ldcg((const float4*)(hprevG + (size_t)(b0 + fr1) * Hn + pj * 32 + fq1 * 4));
                ra[j] = make_uint4(f2tf32(v0.x), f2tf32(v0.y), f2tf32(v0.z), f2tf32(v0.w));
                rb[j] = make_uint4(f2tf32(v1.x), f2tf32(v1.y), f2tf32(v1.z), f2tf32(v1.w));
            }
            #pragma unroll
            for (int j = 0; j < 4; j++) {
                const int pj = (nblk + 1 + j) & 7;
                *(uint4*)&Hs[fr0 * HST + pj * 32 + fq0 * 4] = ra[j];
                *(uint4*)&Hs[fr1 * HST + pj * 32 + fq1 * 4] = rb[j];
            }
            #pragma unroll
            for (int j = 4; j < 7; j++) {
                const int pj = (nblk + 1 + j) & 7;
                float4 v0 = __ldcg((const float4*)(hprevG + (size_t)(b0 + fr0) * Hn + pj * 32 + fq0 * 4));
                float4 v1 = __ldcg((const float4*)(hprevG + (size_t)(b0 + fr1) * Hn + pj * 32 + fq1 * 4));
                ra[j - 4] = make_uint4(f2tf32(v0.x), f2tf32(v0.y), f2tf32(v0.z), f2tf32(v0.w));
                rb[j - 4] = make_uint4(f2tf32(v1.x), f2tf32(v1.y), f2tf32(v1.z), f2tf32(v1.w));
            }
            #pragma unroll
            for (int j = 4; j < 7; j++) {
                const int pj = (nblk + 1 + j) & 7;
                *(uint4*)&Hs[fr0 * HST + pj * 32 + fq0 * 4] = ra[j - 4];
                *(uint4*)&Hs[fr1 * HST + pj * 32 + fq1 * 4] = rb[j - 4];
            }
            __syncthreads();

            // mma all 7 peer chunks back-to-back
            #pragma unroll
            for (int j = 0; j < 7; j++) {
                const int pj = (nblk + 1 + j) & 7;
                mma_chunk(Hs, Ws, pj, mwarp, slice, gid, tig, acc);
            }
        }

        __syncthreads();   // all mma done before epilogue overwrites own Hs chunk

        // epilogue: gates + h update; own chunk -> Hs (t+1) + pb (peers) + hseq16
        #pragma unroll
        for (int idx = 0; idx < 4; idx++) {
            const int mt = idx >> 1, rh = idx & 1;
            const int row = mwarp + mt * 16 + rh * 8 + gid;    // 0..63
            const int b = b0 + row;
            float outv[2];
            #pragma unroll
            for (int jj = 0; jj < 2; jj++) {
                float rv = acc[mt][0][rh * 2 + jj];
                float zv = acc[mt][1][rh * 2 + jj];
                float nv = acc[mt][2][rh * 2 + jj];
                float gvr = (jj == 0) ? gr[idx].x : gr[idx].y;
                float gvz = (jj == 0) ? gz[idx].x : gz[idx].y;
                float gvn = (jj == 0) ? gn[idx].x : gn[idx].y;
                float bnn = (jj == 0) ? bn2.x : bn2.y;
                float r = __fdividef(1.f, 1.f + __expf(-(gvr + rv)));
                float z = __fdividef(1.f, 1.f + __expf(-(gvz + zv)));
                float aarg = gvn + r * (nv + bnn);
                float e = __expf(2.f * aarg);
                float nn = 1.f - __fdividef(2.f, e + 1.f);
                outv[jj] = (1.f - z) * nn + z * hpr[idx][jj];
            }
            float2 o2 = make_float2(outv[0], outv[1]);
            *(float2*)&hout[(size_t)b * Hn + n0c] = o2;
            if (mode == 0)
                *(__half2*)(hseq16 + ((size_t)t * Bn + b) * Hn + n0c) = __float22half2_rn(o2);
            *(uint2*)&Hs[row * HST + n0c] = make_uint2(f2tf32(outv[0]), f2tf32(outv[1]));
            hpr[idx][0] = outv[0]; hpr[idx][1] = outv[1];
        }

        __syncthreads();   // all threads' stores ordered before the release arrive
        if (tid == 0) red_release_add1(&g_arr[(grp8 + nblk) * 32]);
    }

    // finalize: reset counters for the next launch / graph replay
    if (tid == 0) red_release_add1(&g_done[grp * 32]);
    if (tid == 0 && nblk == 0) {
        wait_ge(&g_done[grp * 32], 8u);
        #pragma unroll
        for (int j = 0; j < 8; j++) atomicExch(&g_arr[(grp8 + j) * 32], 0u);
        atomicExch(&g_done[grp * 32], 0u);
    }
}

// ---------------- soft cluster assignment q (Student-t, alpha=1) ----------------
__global__ __launch_bounds__(256) void qkernel(
    const float* __restrict__ z, const float* __restrict__ centers, float* __restrict__ q)
{
    __shared__ float cs[Kn * Hn];
    for (int i = threadIdx.x; i < Kn * Hn; i += 256) cs[i] = centers[i];
    __syncthreads();
    int warp = threadIdx.x >> 5, lane = threadIdx.x & 31;
    int b = blockIdx.x * 8 + warp;
    const float* zr = z + (size_t)b * Hn;
    float zv[8];
    #pragma unroll
    for (int i = 0; i < 8; i++) zv[i] = zr[lane + i * 32];
    float qk[Kn]; float s = 0.f;
    #pragma unroll
    for (int k = 0; k < Kn; k++) {
        float d2 = 0.f;
        #pragma unroll
        for (int i = 0; i < 8; i++) {
            float d = zv[i] - cs[k * Hn + lane + i * 32];
            d2 = fmaf(d, d, d2);
        }
        #pragma unroll
        for (int o = 16; o; o >>= 1) d2 += __shfl_xor_sync(0xffffffffu, d2, o);
        qk[k] = 1.f / (1.f + d2);
        s += qk[k];
    }
    if (lane == 0) {
        float inv = 1.f / s;
        #pragma unroll
        for (int k = 0; k < Kn; k++) q[b * Kn + k] = qk[k] * inv;
    }
}

// ---------------- final: logits + q-weighted combine ----------------
__global__ __launch_bounds__(256) void expert_out(
    const float* __restrict__ h2,  // [K,B,E2]
    const float* __restrict__ W3,  // [K,C,E2]
    const float* __restrict__ b3,  // [K,C]
    const float* __restrict__ q,   // [B,K]
    float* __restrict__ out)       // [B,C]
{
    int warp = threadIdx.x >> 5, lane = threadIdx.x & 31;
    int b = blockIdx.x * 8 + warp;
    float p0 = 0.f, p1 = 0.f;
    #pragma unroll
    for (int k = 0; k < Kn; k++) {
        const float* hr = h2 + ((size_t)k * Bn + b) * E2n;
        const float* w0 = W3 + (size_t)(k * 2 + 0) * E2n;
        const float* w1 = W3 + (size_t)(k * 2 + 1) * E2n;
        float d0 = 0.f, d1 = 0.f;
        #pragma unroll
        for (int i = 0; i < 8; i++) {
            float hv = hr[lane + i * 32];
            d0 = fmaf(hv, w0[lane + i * 32], d0);
            d1 = fmaf(hv, w1[lane + i * 32], d1);
        }
        #pragma unroll
        for (int o = 16; o; o >>= 1) {
            d0 += __shfl_xor_sync(0xffffffffu, d0, o);
            d1 += __shfl_xor_sync(0xffffffffu, d1, o);
        }
        float qv = q[b * Kn + k];
        p0 += qv * (d0 + b3[k * 2 + 0]);
        p1 += qv * (d1 + b3[k * 2 + 1]);
    }
    if (lane == 0) { out[b * 2 + 0] = p0; out[b * 2 + 1] = p1; }
}

// ---------------- launch ----------------
extern "C" void kernel_launch(void* const* d_in, const int* in_sizes, int n_in,
                              void* d_out, int out_size)
{
    const float* x      = (const float*)d_in[0];
    const float* W_ih0  = (const float*)d_in[1];
    const float* W_hh0  = (const float*)d_in[2];
    const float* b_ih0  = (const float*)d_in[3];
    const float* b_hh0  = (const float*)d_in[4];
    const float* W_ih1  = (const float*)d_in[5];
    const float* W_hh1  = (const float*)d_in[6];
    const float* b_ih1  = (const float*)d_in[7];
    const float* b_hh1  = (const float*)d_in[8];
    const float* cc     = (const float*)d_in[9];
    const float* eW1    = (const float*)d_in[10];
    const float* eb1    = (const float*)d_in[11];
    const float* eW2    = (const float*)d_in[12];
    const float* eb2    = (const float*)d_in[13];
    const float* eW3    = (const float*)d_in[14];
    const float* eb3    = (const float*)d_in[15];
    float* out = (float*)d_out;

    __half *gi16, *hseq16;
    float *hb0, *hb1, *q, *wih0, *wih1, *wp0, *wp1, *bs0, *bs1, *we1, *we2, *h1, *h2;
    cudaGetSymbolAddress((void**)&gi16,   g_gi16);
    cudaGetSymbolAddress((void**)&hseq16, g_hseq16);
    cudaGetSymbolAddress((void**)&hb0,  g_hbuf0);
    cudaGetSymbolAddress((void**)&hb1,  g_hbuf1);
    cudaGetSymbolAddress((void**)&q,    g_q);
    cudaGetSymbolAddress((void**)&wih0, g_Wt_ih0);
    cudaGetSymbolAddress((void**)&wih1, g_Wt_ih1);
    cudaGetSymbolAddress((void**)&wp0,  g_wp0);
    cudaGetSymbolAddress((void**)&wp1,  g_wp1);
    cudaGetSymbolAddress((void**)&bs0,  g_bsum0);
    cudaGetSymbolAddress((void**)&bs1,  g_bsum1);
    cudaGetSymbolAddress((void**)&we1,  g_Wt_e1);
    cudaGetSymbolAddress((void**)&we2,  g_Wt_e2);
    cudaGetSymbolAddress((void**)&h1,   g_h1);
    cudaGetSymbolAddress((void**)&h2,   g_h2);

    static int smem_set = 0;
    const int SMEM_GRU = (256 * WST + 64 * HST) * 4;  // 177,152 B
    if (!smem_set) {
        cudaFuncSetAttribute(gru_layer, cudaFuncAttributeMaxDynamicSharedMemorySize, SMEM_GRU);
        smem_set = 1;
    }

    // ---- launch 0: all transposes fused ----
    TJobs js;
    js.j[0] = { W_ih0, wih0, 3 * Hn, In,  In  / 32, (3 * Hn / 32) * (In  / 32), 0 };
    js.j[1] = { W_ih1, wih1, 3 * Hn, Hn,  Hn  / 32, (3 * Hn / 32) * (Hn  / 32), 0 };
    js.j[2] = { eW1,   we1,  E1n,    Hn,  Hn  / 32, (E1n / 32) * (Hn  / 32), 0 };
    js.j[3] = { eW2,   we2,  E2n,    E1n, E1n / 32, (E2n / 32) * (E1n / 32), 0 };
    js.j[1].off = js.j[0].off + js.j[0].tpb;
    js.j[2].off = js.j[1].off + js.j[1].tpb;
    js.j[3].off = js.j[2].off + js.j[2].tpb * Kn;
    int totalTiles = js.j[3].off + js.j[3].tpb * Kn;
    transpose_all<<<totalTiles, dim3(32, 8)>>>(js);

    // ---- launch 1: pack W_hh for both layers ----
    pack_whh<<<dim3(8, 8, 2), 256>>>(W_hh0, W_hh1, wp0, wp1);

    // ---- launches 2,3: fold b_hh(r,z) into gi bias ----
    bias_one<<<1, 3 * Hn>>>(b_ih0, b_hh0, bs0);
    bias_one<<<1, 3 * Hn>>>(b_ih1, b_hh1, bs1);

    const int M0 = Tn * Bn;  // 131072

    // ---- gi0 = x @ W_ih0^T + bsum0 (tf32), stored fp16 [T,B,3H] ----
    gemm_tf32<<<dim3(3 * Hn / 128, M0 / 128), 256>>>(
        x, wih0, bs0, gi16, M0, 3 * Hn, In, In, /*amode=*/1, /*ahalf=*/0, /*outhalf=*/1);

    // ---- layer-0 recurrence: ONE persistent launch (stores hseq16 fp16) ----
    gru_layer<<<NCTA, 256, SMEM_GRU>>>(gi16, wp0, b_hh0, hseq16, hb0, hb1, 0);

    // ---- gi1 = h_l0 @ W_ih1^T + bsum1 (tf32, A fp16, out fp16) ----
    gemm_tf32<<<dim3(3 * Hn / 128, M0 / 128), 256>>>(
        hseq16, wih1, bs1, gi16, M0, 3 * Hn, Hn, Hn, /*amode=*/0, /*ahalf=*/1, /*outhalf=*/1);

    // ---- layer-1 recurrence: ONE persistent launch (final h in hb0) ----
    gru_layer<<<NCTA, 256, SMEM_GRU>>>(gi16, wp1, b_hh1, nullptr, hb0, hb1, 1);

    // ---- q [B,K] ----
    qkernel<<<Bn / 8, 256>>>(hb0, cc, q);

    // ---- experts (fp32 exact, batched over K in grid.z) ----
    gemm128<<<dim3(E1n / 128, Bn / 128, Kn), 256>>>(
        hb0, we1, eb1, h1, Bn, E1n, Hn, Hn, 0, /*relu=*/1,
        0, (long long)Hn * E1n, E1n, (long long)Bn * E1n);
    gemm128<<<dim3(E2n / 128, Bn / 128, Kn), 256>>>(
        h1, we2, eb2, h2, Bn, E2n, E1n, E1n, 0, /*relu=*/1,
        (long long)Bn * E1n, (long long)E1n * E2n, E2n, (long long)Bn * E2n);

    // ---- logits + q-weighted combine -> out [B,C] ----
    expert_out<<<Bn / 8, 256>>>(h2, eW3, eb3, q, out);
}

// round 15
// speedup vs baseline: 1.0895x; 1.0895x over previous
#include <cuda_runtime.h>
#include <math.h>

// Problem constants
#define Tn 128
#define Bn 1024
#define In 128
#define Hn 256
#define Kn 8
#define E1n 512
#define E2n 256
#define NCTA 128
#define NGRP 16

// smem strides for mma GRU (bank-conflict-free fragment loads)
#define WST 108
#define HST 260

// ---------------- device scratch (no allocations allowed) ----------------
__device__ __align__(256) float g_gi[(size_t)Tn * Bn * 3 * Hn];
__device__ __align__(256) float g_hseq[(size_t)Tn * Bn * Hn];
__device__ __align__(256) float g_hbuf0[Bn * Hn];
__device__ __align__(256) float g_hbuf1[Bn * Hn];
__device__ __align__(256) float g_q[Bn * Kn];
__device__ __align__(256) float g_Wt_ih0[In * 3 * Hn];
__device__ __align__(256) float g_Wt_ih1[Hn * 3 * Hn];
__device__ __align__(256) float g_wp0[8 * Hn * 96];
__device__ __align__(256) float g_wp1[8 * Hn * 96];
__device__ __align__(256) float g_bsum0[3 * Hn];
__device__ __align__(256) float g_bsum1[3 * Hn];
__device__ __align__(256) float g_Wt_e1[Kn * Hn * E1n];
__device__ __align__(256) float g_Wt_e2[Kn * E1n * E2n];
__device__ __align__(256) float g_h1[(size_t)Kn * Bn * E1n];
__device__ __align__(256) float g_h2[(size_t)Kn * Bn * E2n];

// per-(group, producer) monotonic arrive counters + per-group done counters
__device__ __align__(256) unsigned g_arr[NGRP * 8 * 32];   // 128B stride per counter
__device__ __align__(256) unsigned g_done[NGRP * 32];

// ---------------- f32x2 packed math helpers (Blackwell FFMA2) ----------------
__device__ __forceinline__ unsigned long long pack2(float x, float y) {
    unsigned long long r;
    asm("mov.b64 %0, {%1, %2};" : "=l"(r) : "f"(x), "f"(y));
    return r;
}
__device__ __forceinline__ void ffma2(unsigned long long& d, unsigned long long a, unsigned long long b) {
    asm("fma.rn.f32x2 %0, %1, %2, %0;" : "+l"(d) : "l"(a), "l"(b));
}
__device__ __forceinline__ float2 unpack2(unsigned long long v) {
    float2 f;
    asm("mov.b64 {%0, %1}, %2;" : "=f"(f.x), "=f"(f.y) : "l"(v));
    return f;
}
// pure busy-spin acquire wait: NO __nanosleep (sleep wake latency sat on the
// inter-CTA critical path twice per step)
__device__ __forceinline__ void wait_ge(const unsigned* p, unsigned v) {
    unsigned x;
    do {
        asm volatile("ld.acquire.gpu.global.u32 %0, [%1];" : "=r"(x) : "l"(p) : "memory");
    } while (x < v);
}
__device__ __forceinline__ void red_release_add1(unsigned* p) {
    asm volatile("red.release.gpu.global.add.u32 [%0], %1;" :: "l"(p), "r"(1u) : "memory");
}

// ---------------- tf32 mma helpers ----------------
__device__ __forceinline__ unsigned f2tf32(float x) {
    unsigned u;
    asm("cvt.rna.tf32.f32 %0, %1;" : "=r"(u) : "f"(x));
    return u;
}
__device__ __forceinline__ void mma_tf32(float* c, const unsigned* a, const unsigned* b) {
    asm volatile(
        "mma.sync.aligned.m16n8k8.row.col.f32.tf32.tf32.f32 "
        "{%0,%1,%2,%3}, {%4,%5,%6,%7}, {%8,%9}, {%0,%1,%2,%3};"
        : "+f"(c[0]), "+f"(c[1]), "+f"(c[2]), "+f"(c[3])
        : "r"(a[0]), "r"(a[1]), "r"(a[2]), "r"(a[3]), "r"(b[0]), "r"(b[1]));
}

// ---------------- fused transpose (all weight transposes in ONE launch) ----------------
struct TJob { const float* in; float* out; int R, C, tC, tpb, off; };
struct TJobs { TJob j[4]; };

__global__ void transpose_all(TJobs js)
{
    __shared__ float tile[32][33];
    int bx = blockIdx.x;
    int ji = 0;
    if (bx >= js.j[1].off) ji = 1;
    if (bx >= js.j[2].off) ji = 2;
    if (bx >= js.j[3].off) ji = 3;
    TJob jb = js.j[ji];
    int local = bx - jb.off;
    int batch = local / jb.tpb;
    int rem = local - batch * jb.tpb;
    int cIdx = rem % jb.tC, rIdx = rem / jb.tC;
    size_t boff = (size_t)batch * jb.R * jb.C;
    int c0 = cIdx * 32, r0 = rIdx * 32;
    int tx = threadIdx.x, ty = threadIdx.y;
    #pragma unroll
    for (int i = ty; i < 32; i += 8)
        tile[i][tx] = jb.in[boff + (size_t)(r0 + i) * jb.C + c0 + tx];
    __syncthreads();
    #pragma unroll
    for (int i = ty; i < 32; i += 8)
        jb.out[boff + (size_t)(c0 + i) * jb.R + r0 + tx] = tile[tx][i];
}

// ---------------- pack W_hh into per-nblk contiguous [nblk][k][96] ----------------
__global__ void pack_whh(const float* __restrict__ W0, const float* __restrict__ W1,
                         float* __restrict__ P0, float* __restrict__ P1)
{
    const float* W = blockIdx.z ? W1 : W0;
    float* P = blockIdx.z ? P1 : P0;
    int nblk = blockIdx.x, k0 = blockIdx.y * 32;
    __shared__ float tile[96][33];
    int tx = threadIdx.x & 31, ty = threadIdx.x >> 5;  // 32 x 8
    for (int j = ty; j < 96; j += 8) {
        int row = (j >> 5) * Hn + nblk * 32 + (j & 31);
        tile[j][tx] = W[(size_t)row * Hn + k0 + tx];
    }
    __syncthreads();
    for (int idx = threadIdx.x; idx < 32 * 96; idx += 256) {
        int kk = idx / 96, c = idx - kk * 96;
        P[((size_t)nblk * Hn + k0 + kk) * 96 + c] = tile[c][kk];
    }
}

// ---------------- bias combine (one layer per launch) ----------------
__global__ void bias_one(const float* bih, const float* bhh, float* o)
{
    int i = threadIdx.x;  // 768
    o[i] = bih[i] + (i < 2 * Hn ? bhh[i] : 0.f);
}

// ---------------- tf32 tensor-core GEMM: C = A @ Bt + bias (for gi GEMMs) ----------------
__global__ __launch_bounds__(256, 2) void gemm_tf32(
    const float* __restrict__ A, const float* __restrict__ Bt,
    const float* __restrict__ bias, float* __restrict__ Cmat,
    int M, int N, int K, int lda, int amode)
{
    __shared__ unsigned As[2][128][20];
    __shared__ unsigned Bs[2][16][136];

    const int n0 = blockIdx.x * 128;
    const int m0 = blockIdx.y * 128;
    const int tid = threadIdx.x;
    const int lane = tid & 31, w = tid >> 5;
    const int wm0 = (w >> 2) * 64, wn0 = (w & 3) * 32;
    const int gid = lane >> 2, tig = lane & 3;

    const int arow0 = tid >> 2, aq = tid & 3;
    const int brow0 = tid >> 5, bq = tid & 31;

    size_t ab0, ab1;
    { int m = m0 + arow0;
      ab0 = (amode == 0) ? (size_t)m * lda
                         : ((size_t)(m & (Bn - 1)) * Tn + (m >> 10)) * (size_t)lda; }
    { int m = m0 + arow0 + 64;
      ab1 = (amode == 0) ? (size_t)m * lda
                         : ((size_t)(m & (Bn - 1)) * Tn + (m >> 10)) * (size_t)lda; }
    const float* Ap0 = A + ab0 + aq * 4;
    const float* Ap1 = A + ab1 + aq * 4;
    const float* Bp0 = Bt + (size_t)brow0 * N + n0 + bq * 4;
    const float* Bp1 = Bt + (size_t)(brow0 + 8) * N + n0 + bq * 4;

    float c[4][4][4];
    #pragma unroll
    for (int mi = 0; mi < 4; mi++)
        #pragma unroll
        for (int ni = 0; ni < 4; ni++)
            #pragma unroll
            for (int r = 0; r < 4; r++) c[mi][ni][r] = 0.f;

    float4 pa0 = *(const float4*)(Ap0);
    float4 pa1 = *(const float4*)(Ap1);
    float4 pb0 = *(const float4*)(Bp0);
    float4 pb1 = *(const float4*)(Bp1);
    *(uint4*)&As[0][arow0][aq * 4] = make_uint4(f2tf32(pa0.x), f2tf32(pa0.y), f2tf32(pa0.z), f2tf32(pa0.w));
    *(uint4*)&As[0][arow0 + 64][aq * 4] = make_uint4(f2tf32(pa1.x), f2tf32(pa1.y), f2tf32(pa1.z), f2tf32(pa1.w));
    *(uint4*)&Bs[0][brow0][bq * 4] = make_uint4(f2tf32(pb0.x), f2tf32(pb0.y), f2tf32(pb0.z), f2tf32(pb0.w));
    *(uint4*)&Bs[0][brow0 + 8][bq * 4] = make_uint4(f2tf32(pb1.x), f2tf32(pb1.y), f2tf32(pb1.z), f2tf32(pb1.w));
    __syncthreads();

    const int nit = K >> 4;
    for (int it = 0; it < nit; ++it) {
        const int cur = it & 1;
        const bool more = (it + 1) < nit;
        if (more) {
            const int k0 = (it + 1) << 4;
            pa0 = *(const float4*)(Ap0 + k0);
            pa1 = *(const float4*)(Ap1 + k0);
            pb0 = *(const float4*)(Bp0 + (size_t)k0 * N);
            pb1 = *(const float4*)(Bp1 + (size_t)k0 * N);
        }
        #pragma unroll
        for (int ks = 0; ks < 2; ks++) {
            const int ac = ks * 8 + tig;
            unsigned af[4][4];
            #pragma unroll
            for (int mi = 0; mi < 4; mi++) {
                const int rb = wm0 + mi * 16 + gid;
                af[mi][0] = As[cur][rb][ac];
                af[mi][1] = As[cur][rb + 8][ac];
                af[mi][2] = As[cur][rb][ac + 4];
                af[mi][3] = As[cur][rb + 8][ac + 4];
            }
            const int bk = ks * 8 + tig;
            unsigned bf[4][2];
            #pragma unroll
            for (int ni = 0; ni < 4; ni++) {
                const int nn = wn0 + ni * 8 + gid;
                bf[ni][0] = Bs[cur][bk][nn];
                bf[ni][1] = Bs[cur][bk + 4][nn];
            }
            #pragma unroll
            for (int mi = 0; mi < 4; mi++)
                #pragma unroll
                for (int ni = 0; ni < 4; ni++)
                    mma_tf32(c[mi][ni], af[mi], bf[ni]);
        }
        if (more) {
            const int nb = cur ^ 1;
            *(uint4*)&As[nb][arow0][aq * 4] = make_uint4(f2tf32(pa0.x), f2tf32(pa0.y), f2tf32(pa0.z), f2tf32(pa0.w));
            *(uint4*)&As[nb][arow0 + 64][aq * 4] = make_uint4(f2tf32(pa1.x), f2tf32(pa1.y), f2tf32(pa1.z), f2tf32(pa1.w));
            *(uint4*)&Bs[nb][brow0][bq * 4] = make_uint4(f2tf32(pb0.x), f2tf32(pb0.y), f2tf32(pb0.z), f2tf32(pb0.w));
            *(uint4*)&Bs[nb][brow0 + 8][bq * 4] = make_uint4(f2tf32(pb1.x), f2tf32(pb1.y), f2tf32(pb1.z), f2tf32(pb1.w));
            __syncthreads();
        }
    }

    #pragma unroll
    for (int ni = 0; ni < 4; ni++) {
        const int cc = n0 + wn0 + ni * 8 + tig * 2;
        const float2 b2 = *(const float2*)&bias[cc];
        #pragma unroll
        for (int mi = 0; mi < 4; mi++) {
            const int r = m0 + wm0 + mi * 16 + gid;
            float2 v0 = make_float2(c[mi][ni][0] + b2.x, c[mi][ni][1] + b2.y);
            float2 v1 = make_float2(c[mi][ni][2] + b2.x, c[mi][ni][3] + b2.y);
            *(float2*)&Cmat[(size_t)r * N + cc] = v0;
            *(float2*)&Cmat[(size_t)(r + 8) * N + cc] = v1;
        }
    }
}

// ---------------- double-buffered 128x128x16 fp32x2 GEMM (experts) ----------------
__global__ __launch_bounds__(256, 2) void gemm128(
    const float* __restrict__ A, const float* __restrict__ Bt,
    const float* __restrict__ bias, float* __restrict__ Cmat,
    int M, int N, int K, int lda, int amode, int relu,
    long long sA, long long sB, long long sBias, long long sC)
{
    const int bz = blockIdx.z;
    A    += (size_t)sA * bz;
    Bt   += (size_t)sB * bz;
    bias += (size_t)sBias * bz;
    Cmat += (size_t)sC * bz;
    const int n0 = blockIdx.x * 128;
    const int m0 = blockIdx.y * 128;

    __shared__ float As[2][16][132];
    __shared__ float Bs[2][16][128];

    const int tid = threadIdx.x;
    const int tx = tid & 15, ty = tid >> 4;
    const int arow0 = tid >> 2, aq = tid & 3;
    const int brow0 = tid >> 5, bq = tid & 31;

    size_t ab0, ab1;
    { int m = m0 + arow0;
      ab0 = (amode == 0) ? (size_t)m * lda
                         : ((size_t)(m & (Bn - 1)) * Tn + (m >> 10)) * (size_t)lda; }
    { int m = m0 + arow0 + 64;
      ab1 = (amode == 0) ? (size_t)m * lda
                         : ((size_t)(m & (Bn - 1)) * Tn + (m >> 10)) * (size_t)lda; }
    const float* Ap0 = A + ab0 + aq * 4;
    const float* Ap1 = A + ab1 + aq * 4;
    const float* Bp0 = Bt + (size_t)brow0 * N + n0 + bq * 4;
    const float* Bp1 = Bt + (size_t)(brow0 + 8) * N + n0 + bq * 4;

    unsigned long long acc[8][4];
    #pragma unroll
    for (int i = 0; i < 8; i++)
        #pragma unroll
        for (int j = 0; j < 4; j++) acc[i][j] = 0ull;

    float4 pa0 = *(const float4*)(Ap0);
    float4 pa1 = *(const float4*)(Ap1);
    float4 pb0 = *(const float4*)(Bp0);
    float4 pb1 = *(const float4*)(Bp1);
    As[0][aq * 4 + 0][arow0] = pa0.x; As[0][aq * 4 + 1][arow0] = pa0.y;
    As[0][aq * 4 + 2][arow0] = pa0.z; As[0][aq * 4 + 3][arow0] = pa0.w;
    As[0][aq * 4 + 0][arow0 + 64] = pa1.x; As[0][aq * 4 + 1][arow0 + 64] = pa1.y;
    As[0][aq * 4 + 2][arow0 + 64] = pa1.z; As[0][aq * 4 + 3][arow0 + 64] = pa1.w;
    *(float4*)&Bs[0][brow0][bq * 4] = pb0;
    *(float4*)&Bs[0][brow0 + 8][bq * 4] = pb1;
    __syncthreads();

    const int nit = K >> 4;
    for (int it = 0; it < nit; ++it) {
        const int cur = it & 1;
        const bool more = (it + 1) < nit;
        if (more) {
            const int k0 = (it + 1) << 4;
            pa0 = *(const float4*)(Ap0 + k0);
            pa1 = *(const float4*)(Ap1 + k0);
            pb0 = *(const float4*)(Bp0 + (size_t)k0 * N);
            pb1 = *(const float4*)(Bp1 + (size_t)k0 * N);
        }
        #pragma unroll
        for (int k = 0; k < 16; k++) {
            float4 aA = *(const float4*)&As[cur][k][ty * 4];
            float4 aB = *(const float4*)&As[cur][k][64 + ty * 4];
            ulonglong2 bA = *(const ulonglong2*)&Bs[cur][k][tx * 4];
            ulonglong2 bB = *(const ulonglong2*)&Bs[cur][k][64 + tx * 4];
            unsigned long long b2[4] = { bA.x, bA.y, bB.x, bB.y };
            float a_[8] = { aA.x, aA.y, aA.z, aA.w, aB.x, aB.y, aB.z, aB.w };
            #pragma unroll
            for (int i = 0; i < 8; i++) {
                unsigned long long a2 = pack2(a_[i], a_[i]);
                #pragma unroll
                for (int j = 0; j < 4; j++) ffma2(acc[i][j], a2, b2[j]);
            }
        }
        if (more) {
            const int nb = cur ^ 1;
            As[nb][aq * 4 + 0][arow0] = pa0.x; As[nb][aq * 4 + 1][arow0] = pa0.y;
            As[nb][aq * 4 + 2][arow0] = pa0.z; As[nb][aq * 4 + 3][arow0] = pa0.w;
            As[nb][aq * 4 + 0][arow0 + 64] = pa1.x; As[nb][aq * 4 + 1][arow0 + 64] = pa1.y;
            As[nb][aq * 4 + 2][arow0 + 64] = pa1.z; As[nb][aq * 4 + 3][arow0 + 64] = pa1.w;
            *(float4*)&Bs[nb][brow0][bq * 4] = pb0;
            *(float4*)&Bs[nb][brow0 + 8][bq * 4] = pb1;
            __syncthreads();
        }
    }

    #pragma unroll
    for (int i = 0; i < 8; i++) {
        int r = (i < 4) ? (ty * 4 + i) : (64 + ty * 4 + (i - 4));
        size_t crow = (size_t)(m0 + r) * N;
        #pragma unroll
        for (int j = 0; j < 4; j++) {
            int c = n0 + ((j < 2) ? (tx * 4 + j * 2) : (64 + tx * 4 + (j - 2) * 2));
            float2 v = unpack2(acc[i][j]);
            v.x += bias[c]; v.y += bias[c + 1];
            if (relu) { v.x = fmaxf(v.x, 0.f); v.y = fmaxf(v.y, 0.f); }
            *(float2*)&Cmat[crow + c] = v;
        }
    }
}

// ---------------- chunk mma: 4 k-tiles (32 k) of m16n8k8 across 3 gates ----------------
__device__ __forceinline__ void mma_chunk(
    const unsigned* __restrict__ Hs, const unsigned* __restrict__ Ws,
    int j, int mwarp, int slice, int gid, int tig, float (&acc)[2][3][4])
{
    #pragma unroll
    for (int kt = 0; kt < 4; kt++) {
        const int kk = j * 32 + kt * 8;
        unsigned a[2][4];
        #pragma unroll
        for (int mt = 0; mt < 2; mt++) {
            const unsigned* hb = Hs + (mwarp + mt * 16 + gid) * HST + kk + tig;
            a[mt][0] = hb[0];
            a[mt][1] = hb[8 * HST];
            a[mt][2] = hb[4];
            a[mt][3] = hb[8 * HST + 4];
        }
        unsigned bf[3][2];
        #pragma unroll
        for (int g = 0; g < 3; g++) {
            const int n = g * 32 + slice * 8 + gid;
            bf[g][0] = Ws[(kk + tig) * WST + n];
            bf[g][1] = Ws[(kk + tig + 4) * WST + n];
        }
        #pragma unroll
        for (int mt = 0; mt < 2; mt++)
            #pragma unroll
            for (int g = 0; g < 3; g++)
                mma_tf32(acc[mt][g], a[mt], bf[g]);
    }
}

// ---------------- persistent GRU layer: per-producer dataflow, batched exchange ----
// 128 CTAs. bid = grp*8 + nblk. CTA: 64 batch rows x (3 gates x 32 cols), K=256.
// Per step: own-chunk mma -> PARALLEL wait on 7 peer counters -> batched LDG of all
// 7 chunks (MLP 14) -> STS -> ONE sync -> mma 7 chunks -> epilogue -> release.
__global__ __launch_bounds__(256, 1) void gru_layer(
    const float* __restrict__ gi,    // [T,B,3H] with b_ih + b_hh(r,z) folded
    const float* __restrict__ wpack, // [8][256][96] fp32
    const float* __restrict__ bhh,   // original b_hh (n-gate slice used)
    float* __restrict__ hseq,
    float* __restrict__ pb0, float* __restrict__ pb1,
    int mode)
{
    extern __shared__ unsigned smu[];
    unsigned* Ws = smu;                 // [256][WST] tf32 bits
    unsigned* Hs = smu + 256 * WST;     // [64][HST]  tf32 bits

    const int bid = blockIdx.x;
    const int nblk = bid & 7;
    const int grp = bid >> 3;
    const int b0 = grp << 6;
    const int tid = threadIdx.x;
    const int lane = tid & 31, w = tid >> 5;
    const int gid = lane >> 2, tig = lane & 3;
    const int slice = w & 3;
    const int mwarp = (w >> 2) * 32;
    const int grp8 = grp * 8;

    // chunk-fill thread mapping (2 float4 per thread per chunk)
    const int fr0 = tid >> 3, fq0 = tid & 7;
    const int fr1 = 32 + (tid >> 3), fq1 = tid & 7;

    // load W slice once, convert to tf32, restride 96 -> WST
    {
        const float* wsrc = wpack + (size_t)nblk * 256 * 96;
        for (int i = tid; i < 256 * 24; i += 256) {
            int k = i / 24, c4 = (i - (i / 24) * 24) * 4;
            float4 v = *(const float4*)(wsrc + (size_t)k * 96 + c4);
            *(uint4*)&Ws[k * WST + c4] = make_uint4(f2tf32(v.x), f2tf32(v.y), f2tf32(v.z), f2tf32(v.w));
        }
    }
    __syncthreads();

    const int n0c = (nblk << 5) + slice * 8 + tig * 2;   // owned global hidden cols
    const float2 bn2 = *(const float2*)&bhh[2 * Hn + n0c];

    float hpr[4][2];   // own h(t-1) values (this thread's previous outputs)
    #pragma unroll
    for (int i = 0; i < 4; i++) { hpr[i][0] = 0.f; hpr[i][1] = 0.f; }

    for (int t = 0; t < Tn; t++) {
        const float* hprevG; float* hout;
        if (mode == 0) {
            hprevG = hseq + (size_t)(t - 1) * (Bn * Hn);
            hout   = hseq + (size_t)t * (Bn * Hn);
        } else {
            hprevG = (t & 1) ? pb1 : pb0;
            hout   = (t & 1) ? pb0 : pb1;
        }

        // hoisted gi loads (independent of peers)
        float2 gr[4], gz[4], gn[4];
        #pragma unroll
        for (int idx = 0; idx < 4; idx++) {
            int b = b0 + mwarp + (idx >> 1) * 16 + (idx & 1) * 8 + gid;
            const float* gp = gi + ((size_t)t * Bn + b) * (3 * Hn);
            gr[idx] = *(const float2*)(gp + n0c);
            gz[idx] = *(const float2*)(gp + Hn + n0c);
            gn[idx] = *(const float2*)(gp + 2 * Hn + n0c);
        }

        float acc[2][3][4];
        #pragma unroll
        for (int mt = 0; mt < 2; mt++)
            #pragma unroll
            for (int g = 0; g < 3; g++)
                #pragma unroll
                for (int r = 0; r < 4; r++) acc[mt][g][r] = 0.f;

        if (t > 0) {
            // own chunk already in Hs from t-1 epilogue: compute while peers finish
            mma_chunk(Hs, Ws, nblk, mwarp, slice, gid, tig, acc);

            // parallel wait: lanes 0..6 each busy-poll one peer counter
            if (tid < 7) {
                const int pj = (nblk + 1 + tid) & 7;
                wait_ge(&g_arr[(grp8 + pj) * 32], (unsigned)t);
            }
            __syncthreads();

            // batched load of all 7 peer chunks (two register waves), then STS
            uint4 ra[4], rb[4];
            #pragma unroll
            for (int j = 0; j < 4; j++) {
                const int pj = (nblk + 1 + j) & 7;
                float4 v0 = __ldcg((const float4*)(hprevG + (size_t)(b0 + fr0) * Hn + pj * 32 + fq0 * 4));
                float4 v1 = __ldcg((const float4*)(hprevG + (size_t)(b0 + fr1) * Hn + pj * 32 + fq1 * 4));
                ra[j] = make_uint4(f2tf32(v0.x), f2tf32(v0.y), f2tf32(v0.z), f2tf32(v0.w));
                rb[j] = make_uint4(f2tf32(v1.x), f2tf32(v1.y), f2tf32(v1.z), f2tf32(v1.w));
            }
            #pragma unroll
            for (int j = 0; j < 4; j++) {
                const int pj = (nblk + 1 + j) & 7;
                *(uint4*)&Hs[fr0 * HST + pj * 32 + fq0 * 4] = ra[j];
                *(uint4*)&Hs[fr1 * HST + pj * 32 + fq1 * 4] = rb[j];
            }
            #pragma unroll
            for (int j = 4; j < 7; j++) {
                const int pj = (nblk + 1 + j) & 7;
                float4 v0 = __ldcg((const float4*)(hprevG + (size_t)(b0 + fr0) * Hn + pj * 32 + fq0 * 4));
                float4 v1 = __ldcg((const float4*)(hprevG + (size_t)(b0 + fr1) * Hn + pj * 32 + fq1 * 4));
                ra[j - 4] = make_uint4(f2tf32(v0.x), f2tf32(v0.y), f2tf32(v0.z), f2tf32(v0.w));
                rb[j - 4] = make_uint4(f2tf32(v1.x), f2tf32(v1.y), f2tf32(v1.z), f2tf32(v1.w));
            }
            #pragma unroll
            for (int j = 4; j < 7; j++) {
                const int pj = (nblk + 1 + j) & 7;
                *(uint4*)&Hs[fr0 * HST + pj * 32 + fq0 * 4] = ra[j - 4];
                *(uint4*)&Hs[fr1 * HST + pj * 32 + fq1 * 4] = rb[j - 4];
            }
            __syncthreads();

            // mma all 7 peer chunks back-to-back
            #pragma unroll
            for (int j = 0; j < 7; j++) {
                const int pj = (nblk + 1 + j) & 7;
                mma_chunk(Hs, Ws, pj, mwarp, slice, gid, tig, acc);
            }
        }

        __syncthreads();   // all mma done before epilogue overwrites own Hs chunk

        // epilogue: gates + h update; own chunk -> Hs (for t+1) + gmem (for peers)
        #pragma unroll
        for (int idx = 0; idx < 4; idx++) {
            const int mt = idx >> 1, rh = idx & 1;
            const int row = mwarp + mt * 16 + rh * 8 + gid;    // 0..63
            const int b = b0 + row;
            float outv[2];
            #pragma unroll
            for (int jj = 0; jj < 2; jj++) {
                float rv = acc[mt][0][rh * 2 + jj];
                float zv = acc[mt][1][rh * 2 + jj];
                float nv = acc[mt][2][rh * 2 + jj];
                float gvr = (jj == 0) ? gr[idx].x : gr[idx].y;
                float gvz = (jj == 0) ? gz[idx].x : gz[idx].y;
                float gvn = (jj == 0) ? gn[idx].x : gn[idx].y;
                float bnn = (jj == 0) ? bn2.x : bn2.y;
                float r = __fdividef(1.f, 1.f + __expf(-(gvr + rv)));
                float z = __fdividef(1.f, 1.f + __expf(-(gvz + zv)));
                float aarg = gvn + r * (nv + bnn);
                float e = __expf(2.f * aarg);
                float nn = 1.f - __fdividef(2.f, e + 1.f);
                outv[jj] = (1.f - z) * nn + z * hpr[idx][jj];
            }
            *(float2*)&hout[(size_t)b * Hn + n0c] = make_float2(outv[0], outv[1]);
            *(uint2*)&Hs[row * HST + n0c] = make_uint2(f2tf32(outv[0]), f2tf32(outv[1]));
            hpr[idx][0] = outv[0]; hpr[idx][1] = outv[1];
        }

        __syncthreads();   // all threads' stores ordered before the release arrive
        if (tid == 0) red_release_add1(&g_arr[(grp8 + nblk) * 32]);
    }

    // finalize: reset counters for the next launch / graph replay
    if (tid == 0) red_release_add1(&g_done[grp * 32]);
    if (tid == 0 && nblk == 0) {
        wait_ge(&g_done[grp * 32], 8u);
        #pragma unroll
        for (int j = 0; j < 8; j++) atomicExch(&g_arr[(grp8 + j) * 32], 0u);
        atomicExch(&g_done[grp * 32], 0u);
    }
}

// ---------------- soft cluster assignment q (Student-t, alpha=1) ----------------
__global__ __launch_bounds__(256) void qkernel(
    const float* __restrict__ z, const float* __restrict__ centers, float* __restrict__ q)
{
    __shared__ float cs[Kn * Hn];
    for (int i = threadIdx.x; i < Kn * Hn; i += 256) cs[i] = centers[i];
    __syncthreads();
    int warp = threadIdx.x >> 5, lane = threadIdx.x & 31;
    int b = blockIdx.x * 8 + warp;
    const float* zr = z + (size_t)b * Hn;
    float zv[8];
    #pragma unroll
    for (int i = 0; i < 8; i++) zv[i] = zr[lane + i * 32];
    float qk[Kn]; float s = 0.f;
    #pragma unroll
    for (int k = 0; k < Kn; k++) {
        float d2 = 0.f;
        #pragma unroll
        for (int i = 0; i < 8; i++) {
            float d = zv[i] - cs[k * Hn + lane + i * 32];
            d2 = fmaf(d, d, d2);
        }
        #pragma unroll
        for (int o = 16; o; o >>= 1) d2 += __shfl_xor_sync(0xffffffffu, d2, o);
        qk[k] = 1.f / (1.f + d2);
        s += qk[k];
    }
    if (lane == 0) {
        float inv = 1.f / s;
        #pragma unroll
        for (int k = 0; k < Kn; k++) q[b * Kn + k] = qk[k] * inv;
    }
}

// ---------------- final: logits + q-weighted combine ----------------
__global__ __launch_bounds__(256) void expert_out(
    const float* __restrict__ h2,  // [K,B,E2]
    const float* __restrict__ W3,  // [K,C,E2]
    const float* __restrict__ b3,  // [K,C]
    const float* __restrict__ q,   // [B,K]
    float* __restrict__ out)       // [B,C]
{
    int warp = threadIdx.x >> 5, lane = threadIdx.x & 31;
    int b = blockIdx.x * 8 + warp;
    float p0 = 0.f, p1 = 0.f;
    #pragma unroll
    for (int k = 0; k < Kn; k++) {
        const float* hr = h2 + ((size_t)k * Bn + b) * E2n;
        const float* w0 = W3 + (size_t)(k * 2 + 0) * E2n;
        const float* w1 = W3 + (size_t)(k * 2 + 1) * E2n;
        float d0 = 0.f, d1 = 0.f;
        #pragma unroll
        for (int i = 0; i < 8; i++) {
            float hv = hr[lane + i * 32];
            d0 = fmaf(hv, w0[lane + i * 32], d0);
            d1 = fmaf(hv, w1[lane + i * 32], d1);
        }
        #pragma unroll
        for (int o = 16; o; o >>= 1) {
            d0 += __shfl_xor_sync(0xffffffffu, d0, o);
            d1 += __shfl_xor_sync(0xffffffffu, d1, o);
        }
        float qv = q[b * Kn + k];
        p0 += qv * (d0 + b3[k * 2 + 0]);
        p1 += qv * (d1 + b3[k * 2 + 1]);
    }
    if (lane == 0) { out[b * 2 + 0] = p0; out[b * 2 + 1] = p1; }
}

// ---------------- launch ----------------
extern "C" void kernel_launch(void* const* d_in, const int* in_sizes, int n_in,
                              void* d_out, int out_size)
{
    const float* x      = (const float*)d_in[0];
    const float* W_ih0  = (const float*)d_in[1];
    const float* W_hh0  = (const float*)d_in[2];
    const float* b_ih0  = (const float*)d_in[3];
    const float* b_hh0  = (const float*)d_in[4];
    const float* W_ih1  = (const float*)d_in[5];
    const float* W_hh1  = (const float*)d_in[6];
    const float* b_ih1  = (const float*)d_in[7];
    const float* b_hh1  = (const float*)d_in[8];
    const float* cc     = (const float*)d_in[9];
    const float* eW1    = (const float*)d_in[10];
    const float* eb1    = (const float*)d_in[11];
    const float* eW2    = (const float*)d_in[12];
    const float* eb2    = (const float*)d_in[13];
    const float* eW3    = (const float*)d_in[14];
    const float* eb3    = (const float*)d_in[15];
    float* out = (float*)d_out;

    float *gi, *hseq, *hb0, *hb1, *q, *wih0, *wih1, *wp0, *wp1, *bs0, *bs1, *we1, *we2, *h1, *h2;
    cudaGetSymbolAddress((void**)&gi,   g_gi);
    cudaGetSymbolAddress((void**)&hseq, g_hseq);
    cudaGetSymbolAddress((void**)&hb0,  g_hbuf0);
    cudaGetSymbolAddress((void**)&hb1,  g_hbuf1);
    cudaGetSymbolAddress((void**)&q,    g_q);
    cudaGetSymbolAddress((void**)&wih0, g_Wt_ih0);
    cudaGetSymbolAddress((void**)&wih1, g_Wt_ih1);
    cudaGetSymbolAddress((void**)&wp0,  g_wp0);
    cudaGetSymbolAddress((void**)&wp1,  g_wp1);
    cudaGetSymbolAddress((void**)&bs0,  g_bsum0);
    cudaGetSymbolAddress((void**)&bs1,  g_bsum1);
    cudaGetSymbolAddress((void**)&we1,  g_Wt_e1);
    cudaGetSymbolAddress((void**)&we2,  g_Wt_e2);
    cudaGetSymbolAddress((void**)&h1,   g_h1);
    cudaGetSymbolAddress((void**)&h2,   g_h2);

    static int smem_set = 0;
    const int SMEM_GRU = (256 * WST + 64 * HST) * 4;  // 177,152 B
    if (!smem_set) {
        cudaFuncSetAttribute(gru_layer, cudaFuncAttributeMaxDynamicSharedMemorySize, SMEM_GRU);
        smem_set = 1;
    }

    // ---- launch 0: all transposes fused ----
    TJobs js;
    js.j[0] = { W_ih0, wih0, 3 * Hn, In,  In  / 32, (3 * Hn / 32) * (In  / 32), 0 };
    js.j[1] = { W_ih1, wih1, 3 * Hn, Hn,  Hn  / 32, (3 * Hn / 32) * (Hn  / 32), 0 };
    js.j[2] = { eW1,   we1,  E1n,    Hn,  Hn  / 32, (E1n / 32) * (Hn  / 32), 0 };
    js.j[3] = { eW2,   we2,  E2n,    E1n, E1n / 32, (E2n / 32) * (E1n / 32), 0 };
    js.j[1].off = js.j[0].off + js.j[0].tpb;
    js.j[2].off = js.j[1].off + js.j[1].tpb;
    js.j[3].off = js.j[2].off + js.j[2].tpb * Kn;
    int totalTiles = js.j[3].off + js.j[3].tpb * Kn;
    transpose_all<<<totalTiles, dim3(32, 8)>>>(js);

    // ---- launch 1: pack W_hh for both layers ----
    pack_whh<<<dim3(8, 8, 2), 256>>>(W_hh0, W_hh1, wp0, wp1);

    // ---- launches 2,3: fold b_hh(r,z) into gi bias ----
    bias_one<<<1, 3 * Hn>>>(b_ih0, b_hh0, bs0);
    bias_one<<<1, 3 * Hn>>>(b_ih1, b_hh1, bs1);

    const int M0 = Tn * Bn;  // 131072

    // ---- launch 4: gi0 = x @ W_ih0^T + bsum0 (tf32), stored [T,B,3H] ----
    gemm_tf32<<<dim3(3 * Hn / 128, M0 / 128), 256>>>(
        x, wih0, bs0, gi, M0, 3 * Hn, In, In, /*amode=*/1);

    // ---- launch 5: layer-0 recurrence, ONE persistent launch ----
    gru_layer<<<NCTA, 256, SMEM_GRU>>>(gi, wp0, b_hh0, hseq, nullptr, nullptr, 0);

    // ---- gi1 = h_l0 @ W_ih1^T + bsum1 (tf32) ----
    gemm_tf32<<<dim3(3 * Hn / 128, M0 / 128), 256>>>(
        hseq, wih1, bs1, gi, M0, 3 * Hn, Hn, Hn, /*amode=*/0);

    // ---- layer-1 recurrence: ONE persistent launch (final h in hb0) ----
    gru_layer<<<NCTA, 256, SMEM_GRU>>>(gi, wp1, b_hh1, nullptr, hb0, hb1, 1);

    // ---- q [B,K] ----
    qkernel<<<Bn / 8, 256>>>(hb0, cc, q);

    // ---- experts (fp32, batched over K in grid.z) ----
    gemm128<<<dim3(E1n / 128, Bn / 128, Kn), 256>>>(
        hb0, we1, eb1, h1, Bn, E1n, Hn, Hn, 0, /*relu=*/1,
        0, (long long)Hn * E1n, E1n, (long long)Bn * E1n);
    gemm128<<<dim3(E2n / 128, Bn / 128, Kn), 256>>>(
        h1, we2, eb2, h2, Bn, E2n, E1n, E1n, 0, /*relu=*/1,
        (long long)Bn * E1n, (long long)E1n * E2n, E2n, (long long)Bn * E2n);

    // ---- logits + q-weighted combine -> out [B,C] ----
    expert_out<<<Bn / 8, 256>>>(h2, eW3, eb3, q, out);
}